// round 7
// baseline (speedup 1.0000x reference)
#include <cuda_runtime.h>
#include <math.h>
#include <stdint.h>

// ---------------- problem constants ----------------
#define NROWS 8192
#define IN_F  512
#define RFF   2048
#define OUT_F 1000
#define KBIG  (3*IN_F)          // 1536: [Dhi | Dlo | Dhi] x [Whi | Whi | Wlo]
#define INV_RFF_SCALAR (1.0f/32.0f)
#define MFF   25.0f

// ---------------- tiling ----------------
#define BM 128
#define BN 128
#define BK 32
#define LDSS 36
#define A_FLOATS (128*LDSS)
#define STAGE_FLOATS (2*128*LDSS)
#define STAGE_BYTES (STAGE_FLOATS*4) // 36864
#define NSTAGE 3
#define NTH 128                      // 4 warps, 2x2 grid, 64x64 warp tiles
#define GRID_P 296                   // persistent grid: 2 CTAs x 148 SMs

// ---------------- device scratch ----------------
__device__ float g_Phi[NROWS*RFF];            // 64 MB tf32(Phi)
__device__ float g_Phi2[NROWS*RFF];           // 64 MB 2*tf32(Phi) (exact)
__device__ float g_Abig[NROWS*KBIG];          // 48 MB
__device__ float g_Bbig[RFF*KBIG];            // 12 MB ([N][K])
__device__ float g_diag_part[16*NROWS];
__device__ int   g_ctr[4];

// ---------------- helpers ----------------
__device__ __forceinline__ uint32_t smem_u32(const void* p) {
    uint32_t r;
    asm("{ .reg .u64 t; cvta.to.shared.u64 t, %1; cvt.u32.u64 %0, t; }" : "=r"(r) : "l"(p));
    return r;
}
__device__ __forceinline__ float to_tf32(float x) {
    float r; asm("cvt.rna.tf32.f32 %0, %1;" : "=f"(r) : "f"(x)); return r;
}
__device__ __forceinline__ void cp16(uint32_t d, const void* s) {
    asm volatile("cp.async.cg.shared.global [%0], [%1], 16;" :: "r"(d), "l"(s));
}
__device__ __forceinline__ void cp16z(uint32_t d, const void* s, uint32_t sz) {
    asm volatile("cp.async.cg.shared.global [%0], [%1], 16, %2;" :: "r"(d), "l"(s), "r"(sz));
}
__device__ __forceinline__ void cp_commit() { asm volatile("cp.async.commit_group;"); }
template <int N> __device__ __forceinline__ void cp_wait() {
    asm volatile("cp.async.wait_group %0;" :: "n"(N));
}
__device__ __forceinline__ void ldsm_x4(uint32_t* r, uint32_t a) {
    asm volatile("ldmatrix.sync.aligned.m8n8.x4.shared.b16 {%0,%1,%2,%3}, [%4];"
        : "=r"(r[0]), "=r"(r[1]), "=r"(r[2]), "=r"(r[3]) : "r"(a));
}
__device__ __forceinline__ void mma_tf32(float* c, const uint32_t* a, const uint32_t* b) {
    asm volatile(
        "mma.sync.aligned.m16n8k8.row.col.f32.tf32.tf32.f32 "
        "{%0,%1,%2,%3}, {%4,%5,%6,%7}, {%8,%9}, {%0,%1,%2,%3};"
        : "+f"(c[0]), "+f"(c[1]), "+f"(c[2]), "+f"(c[3])
        : "r"(a[0]), "r"(a[1]), "r"(a[2]), "r"(a[3]), "r"(b[0]), "r"(b[1]));
}

// ---------------- prep kernels ----------------
__global__ void split_D_k(const float* __restrict__ D, float* __restrict__ A) {
    int idx = blockIdx.x * blockDim.x + threadIdx.x;
    if (idx >= NROWS * IN_F) return;
    int r = idx >> 9, k = idx & (IN_F - 1);
    float x = D[idx], hi = to_tf32(x), lo = x - hi;
    float* p = A + (size_t)r * KBIG;
    p[k] = hi; p[IN_F + k] = to_tf32(lo); p[2 * IN_F + k] = hi;
}

__global__ void split_W_k(const float* __restrict__ W, float* __restrict__ Bb) {
    __shared__ float t[32][33];
    int nb = blockIdx.x * 32, kb = blockIdx.y * 32;
    int tx = threadIdx.x, ty0 = threadIdx.y;
    #pragma unroll
    for (int i = 0; i < 32; i += 8) {
        int ty = ty0 + i;
        t[ty][tx] = W[(size_t)(kb + ty) * RFF + nb + tx];
    }
    __syncthreads();
    #pragma unroll
    for (int i = 0; i < 32; i += 8) {
        int ty = ty0 + i;
        int n = nb + ty, k = kb + tx;
        float x = t[tx][ty], hi = to_tf32(x), lo = x - hi;
        float* p = Bb + (size_t)n * KBIG;
        p[k] = hi; p[IN_F + k] = hi; p[2 * IN_F + k] = to_tf32(lo);
    }
}

// ---------------- persistent mma.sync GEMM (64x64 warp tiles) ----------------
// MODE 0: Phi = tf32(cos(acc+bias)/32), also writes Phi2 = 2*Phi
// MODE 1: diag partial = rowsum(acc*Phi); triangular K; A in {Phi2, Phi}; B = raw cov
// MODE 2: out = (acc+lb)*rsqrt(1+25*diag); B = raw logit_w, zero-filled rows >= 1000
template <int MODE>
__global__ void __launch_bounds__(NTH, 2)
gp_mma(const float* __restrict__ Ag, const float* __restrict__ Ag2,
       const float* __restrict__ Bg,
       const float* __restrict__ bias, float* __restrict__ outp,
       float* __restrict__ outp2,
       const float* __restrict__ phi, float* __restrict__ diagp,
       int* __restrict__ ctr, int nTiles, int K, int nIterFix)
{
    extern __shared__ float dyn[];
    __shared__ int s_tile;
    const int tid = threadIdx.x;
    const int wid = tid >> 5, lane = tid & 31;
    const int g = lane >> 2, t = lane & 3;
    const int warpM = wid >> 1, warpN = wid & 1;   // 2x2 warp grid, 64x64 warp tiles
    const uint32_t sbase = smem_u32(dyn);

    // ldmatrix lane-address offsets (bytes within stage)
    const uint32_t aLdOff = (uint32_t)(((warpM * 64 + ((lane >> 3) & 1) * 8 + (lane & 7)) * LDSS
                                        + ((lane >> 4) & 1) * 4) * 4);
    // B x4: lanes 0-7 -> (n0-7,k0), 8-15 -> (n0-7,k4), 16-23 -> (n8-15,k0), 24-31 -> (n8-15,k4)
    const uint32_t bLdOff = (uint32_t)(A_FLOATS * 4
                                        + ((warpN * 64 + (lane & 7) + ((lane >> 4) & 1) * 8) * LDSS
                                        + ((lane >> 3) & 1) * 4) * 4);

    for (;;) {
        if (tid == 0) s_tile = atomicAdd(ctr, 1);
        __syncthreads();
        const int tile = s_tile;
        if (tile >= nTiles) break;

        int rowTile, colTile, cblk;
        if (MODE == 0)      { cblk = tile & 15; rowTile = (tile >> 4) * BM; }
        else if (MODE == 1) { cblk = 15 - (tile >> 6); rowTile = (tile & 63) * BM; }
        else                { cblk = tile & 7;  rowTile = (tile >> 3) * BM; }
        colTile = cblk * BN;
        const int nIter = (MODE == 1) ? ((colTile + BN) / BK) : nIterFix;

        float acc[4][8][4];
        #pragma unroll
        for (int mt = 0; mt < 4; mt++)
            #pragma unroll
            for (int nt = 0; nt < 8; nt++)
                #pragma unroll
                for (int r = 0; r < 4; r++) acc[mt][nt][r] = 0.0f;

        #define ISSUE(it, s) do {                                                  \
            const int _k0 = (it) * BK;                                             \
            const float* _as = (MODE == 1 && _k0 < colTile) ? Ag2 : Ag;            \
            _Pragma("unroll")                                                      \
            for (int j = 0; j < 8; j++) {                                          \
                int f = tid + NTH * j;                                             \
                int r = f >> 3, q = f & 7;                                         \
                uint32_t d = sbase + (uint32_t)(s) * STAGE_BYTES + (uint32_t)(r * LDSS + q * 4) * 4; \
                cp16(d, _as + (size_t)(rowTile + r) * K + _k0 + q * 4);            \
            }                                                                      \
            _Pragma("unroll")                                                      \
            for (int j = 0; j < 8; j++) {                                          \
                int f = tid + NTH * j;                                             \
                int r = f >> 3, q = f & 7;                                         \
                uint32_t d = sbase + (uint32_t)(s) * STAGE_BYTES + (uint32_t)(A_FLOATS + r * LDSS + q * 4) * 4; \
                if (MODE == 2) {                                                   \
                    int gn = colTile + r;                                          \
                    uint32_t sz = (gn < OUT_F) ? 16u : 0u;                         \
                    const float* src = Bg + (size_t)(sz ? gn : 0) * K + _k0 + q * 4; \
                    cp16z(d, src, sz);                                             \
                } else {                                                           \
                    cp16(d, Bg + (size_t)(colTile + r) * K + _k0 + q * 4);         \
                }                                                                  \
            }                                                                      \
            cp_commit();                                                           \
        } while (0)

        ISSUE(0, 0);
        ISSUE(1, 1);

        int s = 0;
        for (int it = 0; it < nIter; ++it) {
            if (it + 1 < nIter) cp_wait<1>(); else cp_wait<0>();
            __syncthreads();
            if (it + 2 < nIter) ISSUE(it + 2, (s + 2) % NSTAGE);

            const uint32_t aB = sbase + (uint32_t)s * STAGE_BYTES + aLdOff;
            const uint32_t bB = sbase + (uint32_t)s * STAGE_BYTES + bLdOff;
            #pragma unroll
            for (int kk = 0; kk < 4; kk++) {
                uint32_t af[4][4], bf[8][2];
                #pragma unroll
                for (int mt = 0; mt < 4; mt++)
                    ldsm_x4(af[mt], aB + (uint32_t)((mt * 16 * LDSS + kk * 8) * 4));
                #pragma unroll
                for (int np = 0; np < 4; np++) {
                    uint32_t r4[4];
                    ldsm_x4(r4, bB + (uint32_t)((np * 16 * LDSS + kk * 8) * 4));
                    bf[2 * np][0] = r4[0]; bf[2 * np][1] = r4[1];
                    bf[2 * np + 1][0] = r4[2]; bf[2 * np + 1][1] = r4[3];
                }
                #pragma unroll
                for (int mt = 0; mt < 4; mt++)
                    #pragma unroll
                    for (int nt = 0; nt < 8; nt++)
                        mma_tf32(acc[mt][nt], af[mt], bf[nt]);
            }
            s = (s + 1 == NSTAGE) ? 0 : s + 1;
        }
        __syncthreads();

        // ---------------- epilogues ----------------
        if (MODE == 0) {
            #pragma unroll
            for (int mt = 0; mt < 4; mt++)
                #pragma unroll
                for (int h = 0; h < 2; h++) {
                    const int R = rowTile + warpM * 64 + mt * 16 + g + h * 8;
                    float* op  = outp  + (size_t)R * RFF;
                    float* op2 = outp2 + (size_t)R * RFF;
                    #pragma unroll
                    for (int nt = 0; nt < 8; nt++) {
                        const int C = colTile + warpN * 64 + nt * 8 + 2 * t;
                        float2 bb = *(const float2*)(bias + C);
                        float2 o, o2;
                        o.x = to_tf32(cosf(acc[mt][nt][h * 2 + 0] + bb.x) * INV_RFF_SCALAR);
                        o.y = to_tf32(cosf(acc[mt][nt][h * 2 + 1] + bb.y) * INV_RFF_SCALAR);
                        o2.x = 2.0f * o.x; o2.y = 2.0f * o.y;
                        *(float2*)(op + C) = o;
                        *(float2*)(op2 + C) = o2;
                    }
                }
        } else if (MODE == 1) {
            float* red = dyn;  // [128][2]
            #pragma unroll
            for (int mt = 0; mt < 4; mt++)
                #pragma unroll
                for (int h = 0; h < 2; h++) {
                    const int lr = warpM * 64 + mt * 16 + g + h * 8;
                    const float* pr = phi + (size_t)(rowTile + lr) * RFF;
                    float sum = 0.0f;
                    #pragma unroll
                    for (int nt = 0; nt < 8; nt++) {
                        const int C = colTile + warpN * 64 + nt * 8 + 2 * t;
                        float2 p = *(const float2*)(pr + C);
                        sum = fmaf(acc[mt][nt][h * 2 + 0], p.x, sum);
                        sum = fmaf(acc[mt][nt][h * 2 + 1], p.y, sum);
                    }
                    sum += __shfl_xor_sync(0xffffffffu, sum, 1);
                    sum += __shfl_xor_sync(0xffffffffu, sum, 2);
                    if (t == 0) red[lr * 2 + warpN] = sum;
                }
            __syncthreads();
            {
                float sum = red[tid * 2 + 0] + red[tid * 2 + 1];
                diagp[(size_t)cblk * NROWS + rowTile + tid] = sum;
            }
            __syncthreads();
        } else {
            float* scale = dyn;  // [128]
            {
                float dg = 0.0f;
                #pragma unroll
                for (int p = 0; p < 16; p++) dg += diagp[(size_t)p * NROWS + rowTile + tid];
                scale[tid] = rsqrtf(1.0f + MFF * dg);
            }
            __syncthreads();
            #pragma unroll
            for (int mt = 0; mt < 4; mt++)
                #pragma unroll
                for (int h = 0; h < 2; h++) {
                    const int lr = warpM * 64 + mt * 16 + g + h * 8;
                    const int R = rowTile + lr;
                    const float sc = scale[lr];
                    float* op = outp + (size_t)R * OUT_F;
                    #pragma unroll
                    for (int nt = 0; nt < 8; nt++) {
                        const int C = colTile + warpN * 64 + nt * 8 + 2 * t;
                        if (C < OUT_F) {
                            float2 bb = *(const float2*)(bias + C);
                            float2 o;
                            o.x = (acc[mt][nt][h * 2 + 0] + bb.x) * sc;
                            o.y = (acc[mt][nt][h * 2 + 1] + bb.y) * sc;
                            *(float2*)(op + C) = o;
                        }
                    }
                }
            __syncthreads();
        }
        #undef ISSUE
    }
}

// ---------------- host ----------------
extern "C" void kernel_launch(void* const* d_in, const int* in_sizes, int n_in,
                              void* d_out, int out_size)
{
    const float* D   = (const float*)d_in[0];
    const float* W   = (const float*)d_in[1];
    const float* b   = (const float*)d_in[2];
    const float* lw  = (const float*)d_in[3];
    const float* lb  = (const float*)d_in[4];
    const float* cov = (const float*)d_in[5];
    float* out = (float*)d_out;

    float *Phi, *Phi2, *Abig, *Bbig, *diagp;
    int* ctr;
    cudaGetSymbolAddress((void**)&Phi,   g_Phi);
    cudaGetSymbolAddress((void**)&Phi2,  g_Phi2);
    cudaGetSymbolAddress((void**)&Abig,  g_Abig);
    cudaGetSymbolAddress((void**)&Bbig,  g_Bbig);
    cudaGetSymbolAddress((void**)&diagp, g_diag_part);
    cudaGetSymbolAddress((void**)&ctr,   g_ctr);

    const int smem = NSTAGE * STAGE_BYTES;  // 110592 bytes
    cudaFuncSetAttribute(gp_mma<0>, cudaFuncAttributeMaxDynamicSharedMemorySize, smem);
    cudaFuncSetAttribute(gp_mma<1>, cudaFuncAttributeMaxDynamicSharedMemorySize, smem);
    cudaFuncSetAttribute(gp_mma<2>, cudaFuncAttributeMaxDynamicSharedMemorySize, smem);

    cudaMemsetAsync(ctr, 0, 4 * sizeof(int));

    // prep: tf32 hi/lo split operands (GEMM1 only)
    split_D_k<<<(NROWS * IN_F + 255) / 256, 256>>>(D, Abig);
    split_W_k<<<dim3(RFF / 32, IN_F / 32), dim3(32, 8)>>>(W, Bbig);

    // GEMM1: Phi (+Phi2=2*Phi) = tf32(cos(D@W+b)/32), split-tf32, K=1536, 1024 tiles
    gp_mma<0><<<GRID_P, NTH, smem>>>(
        Abig, nullptr, Bbig, b, Phi, Phi2, nullptr, nullptr,
        ctr + 0, 1024, KBIG, KBIG / BK);
    // GEMM2: triangular diag partials; A in {Phi2, Phi}, B = raw cov; 1024 tiles LPT
    gp_mma<1><<<GRID_P, NTH, smem>>>(
        Phi, Phi2, cov, nullptr, nullptr, nullptr, Phi, diagp,
        ctr + 1, 1024, RFF, 0);
    // GEMM3: out = (Phi@lw^T + lb) * rsqrt(1+25*diag); B = raw lw zero-padded; 512 tiles
    gp_mma<2><<<GRID_P, NTH, smem>>>(
        Phi, nullptr, lw, lb, out, nullptr, nullptr, diagp,
        ctr + 2, 512, RFF, RFF / BK);
}